// round 15
// baseline (speedup 1.0000x reference)
#include <cuda_runtime.h>
#include <cuda_fp16.h>
#include <math.h>
#include <stdint.h>

// ---------------- problem constants ----------------
#define B_    32
#define FR_   300
#define D_    2048
#define ED_   4096      // E*D
#define G_    8
#define K_    64
#define FEAT_ 512       // E*D/G
#define VLAD_ 32768     // K*FEAT
#define H_    2048
#define HR_   256       // H/R
#define NC_   3862
#define M_    (B_*FR_)  // 9600
#define N2_   2400      // FR*G
#define BN_EPS 1e-5f
#define L2_EPS 1e-12f

// ---------------- scratch (device globals; no allocs allowed) ----------------
__device__ __align__(128) float g_att[M_ * G_];
__device__ __align__(128) float g_asum[B_ * K_];
__device__ __align__(128) float g_vlad[B_ * FEAT_ * K_];
__device__ __align__(128) float g_vladn[B_ * VLAD_];
__device__ __align__(128) float g_y0[B_ * H_];
__device__ __align__(128) float g_y[B_ * H_];
__device__ __align__(128) float g_z[B_ * HR_];
__device__ __align__(128) float g_yg[B_ * H_];
__device__ __align__(128) float g_w2e[G_ * D_];
__device__ __align__(128) float g_attb[G_];
// fp16 buffers
__device__ __align__(128) __half g_xh[M_ * D_];
__device__ __align__(128) __half g_wh[ED_ * D_];
__device__ __align__(128) __half g_hh[M_ * ED_];
__device__ __align__(128) __half g_c1h[(G_*K_) * ED_];
__device__ __align__(128) __half g_actnh[M_ * (G_*K_)];

// ---------------- K1: fused rownorm + x->fp16 + attention ----------------
__global__ void rownorm_att_kernel(const float* __restrict__ x,
                                   const float* __restrict__ w2e,
                                   const float* __restrict__ attb,
                                   __half* __restrict__ xh, float* __restrict__ att) {
    __shared__ float sx[D_];
    __shared__ float red[8];
    __shared__ float sinv;
    int m = blockIdx.x;
    int t = threadIdx.x;                 // 256 threads
    const float* row = x + (size_t)m * D_;
    float4 v0 = *(const float4*)(row + t * 4);
    float4 v1 = *(const float4*)(row + 1024 + t * 4);
    float s = v0.x * v0.x + v0.y * v0.y + v0.z * v0.z + v0.w * v0.w
            + v1.x * v1.x + v1.y * v1.y + v1.z * v1.z + v1.w * v1.w;
    for (int o = 16; o; o >>= 1) s += __shfl_xor_sync(0xffffffffu, s, o);
    if ((t & 31) == 0) red[t >> 5] = s;
    __syncthreads();
    if (t == 0) {
        float tot = 0.f;
        #pragma unroll
        for (int i = 0; i < 8; i++) tot += red[i];
        sinv = 1.f / fmaxf(sqrtf(tot), L2_EPS);
    }
    __syncthreads();
    float inv = sinv;
    v0.x *= inv; v0.y *= inv; v0.z *= inv; v0.w *= inv;
    v1.x *= inv; v1.y *= inv; v1.z *= inv; v1.w *= inv;
    *(float4*)&sx[t * 4] = v0;
    *(float4*)&sx[1024 + t * 4] = v1;
    __half* dst = xh + (size_t)m * D_;
    __half2 a;
    a.x = __float2half_rn(v0.x); a.y = __float2half_rn(v0.y);
    *(__half2*)&dst[t * 4] = a;
    a.x = __float2half_rn(v0.z); a.y = __float2half_rn(v0.w);
    *(__half2*)&dst[t * 4 + 2] = a;
    a.x = __float2half_rn(v1.x); a.y = __float2half_rn(v1.y);
    *(__half2*)&dst[1024 + t * 4] = a;
    a.x = __float2half_rn(v1.z); a.y = __float2half_rn(v1.w);
    *(__half2*)&dst[1024 + t * 4 + 2] = a;
    __syncthreads();
    // attention: warp g dots sx with w2e[g]
    int g = t >> 5, lane = t & 31;
    const float* wr = w2e + (size_t)g * D_;
    float sa = 0.f;
    for (int k = lane * 2; k < D_; k += 64) {
        float2 w = *(const float2*)&wr[k];
        sa += sx[k] * w.x + sx[k + 1] * w.y;
    }
    for (int o = 16; o; o >>= 1) sa += __shfl_xor_sync(0xffffffffu, sa, o);
    if (lane == 0) {
        float v = sa + attb[g];
        att[m * G_ + g] = 1.f / (1.f + expf(-v));
    }
}

// ---------------- K2: fp32 -> fp16 ----------------
__global__ void tohalf_kernel(const float* __restrict__ src, __half* __restrict__ dst, int n) {
    int i = (blockIdx.x * blockDim.x + threadIdx.x) * 4;
    if (i >= n) return;
    float4 v = *(const float4*)(src + i);
    __half2 a; a.x = __float2half_rn(v.x); a.y = __float2half_rn(v.y);
    __half2 b; b.x = __float2half_rn(v.z); b.y = __float2half_rn(v.w);
    *(__half2*)&dst[i]     = a;
    *(__half2*)&dst[i + 2] = b;
}

// ---------------- K2b: fused transpose -> fp16: c1[R,C] -> c1h[C,R] ----------------
__global__ void transpose_half_kernel(const float* __restrict__ in,
                                      __half* __restrict__ outh, int R, int C) {
    __shared__ float tile[32][33];
    int c0 = blockIdx.x * 32, r0 = blockIdx.y * 32;
    int tx = threadIdx.x & 31, ty = threadIdx.x >> 5;
    #pragma unroll
    for (int i = 0; i < 32; i += 8)
        tile[ty + i][tx] = in[(size_t)(r0 + ty + i) * C + c0 + tx];
    __syncthreads();
    #pragma unroll
    for (int i = 0; i < 32; i += 8) {
        float v = tile[tx][ty + i];
        outh[(size_t)(c0 + ty + i) * R + r0 + tx] = __float2half_rn(v);
    }
}

// ---------------- zero ----------------
__global__ void zero_kernel(float* __restrict__ p, int n) {
    int i = blockIdx.x * blockDim.x + threadIdx.x;
    if (i < n) p[i] = 0.f;
}

// ---------------- K2c: w2e[g][d] += sum_{e in chunk} fc2_w[g][e] * fc1_w[e][d] --------
__global__ void fuse_attw_kernel(const float* __restrict__ fc1_w,
                                 const float* __restrict__ fc2_w,
                                 float* __restrict__ w2e) {
    __shared__ float f2[G_][256];
    int d = blockIdx.x * 256 + threadIdx.x;
    int e0 = blockIdx.y * 256;
    #pragma unroll
    for (int g = 0; g < G_; g++)
        f2[g][threadIdx.x] = fc2_w[(size_t)g * ED_ + e0 + threadIdx.x];
    __syncthreads();
    float acc[G_];
    #pragma unroll
    for (int g = 0; g < G_; g++) acc[g] = 0.f;
    for (int e = 0; e < 256; e++) {
        float w1 = fc1_w[(size_t)(e0 + e) * D_ + d];
        #pragma unroll
        for (int g = 0; g < G_; g++) acc[g] += f2[g][e] * w1;
    }
    #pragma unroll
    for (int g = 0; g < G_; g++) atomicAdd(&w2e[(size_t)g * D_ + d], acc[g]);
}

// ---------------- K2d: attb[g] = fc2_b[g] + dot(fc2_w[g], fc1_b) ----------------
__global__ void fuse_attb_kernel(const float* __restrict__ fc2_w,
                                 const float* __restrict__ fc1_b,
                                 const float* __restrict__ fc2_b,
                                 float* __restrict__ attb) {
    int g = threadIdx.x >> 5, lane = threadIdx.x & 31;
    const float* wr = fc2_w + (size_t)g * ED_;
    float s = 0.f;
    for (int k = lane; k < ED_; k += 32) s += wr[k] * fc1_b[k];
    for (int o = 16; o; o >>= 1) s += __shfl_xor_sync(0xffffffffu, s, o);
    if (lane == 0) attb[g] = s + fc2_b[g];
}

// ---------------- tensor-core GEMM: C[M,N] = A[M,K] * B[N,K]^T  (fp16 1-pass) ---------
#define BM 128
#define BN 128
#define BKK 64
#define SSTRIDE 72
#define MAT_BYTES (128 * SSTRIDE * 2)     // 18432
#define STAGE_B (2 * MAT_BYTES)           // 36864
#define GEMM_SMEM (2 * STAGE_B)           // 73728

__device__ __forceinline__ void cp16(uint32_t dst, const void* src) {
    asm volatile("cp.async.cg.shared.global [%0], [%1], 16;\n" :: "r"(dst), "l"(src));
}
__device__ __forceinline__ void ldsm_x4(uint32_t& r0, uint32_t& r1, uint32_t& r2, uint32_t& r3,
                                        uint32_t addr) {
    asm volatile("ldmatrix.sync.aligned.m8n8.x4.shared.b16 {%0,%1,%2,%3}, [%4];\n"
                 : "=r"(r0), "=r"(r1), "=r"(r2), "=r"(r3) : "r"(addr));
}
__device__ __forceinline__ void ldsm_x4t(uint32_t& r0, uint32_t& r1, uint32_t& r2, uint32_t& r3,
                                         uint32_t addr) {
    asm volatile("ldmatrix.sync.aligned.m8n8.x4.trans.shared.b16 {%0,%1,%2,%3}, [%4];\n"
                 : "=r"(r0), "=r"(r1), "=r"(r2), "=r"(r3) : "r"(addr));
}
__device__ __forceinline__ void mma16816(float* c, const uint32_t* a, const uint32_t* b) {
    asm volatile("mma.sync.aligned.m16n8k16.row.col.f32.f16.f16.f32 "
                 "{%0,%1,%2,%3},{%4,%5,%6,%7},{%8,%9},{%0,%1,%2,%3};\n"
                 : "+f"(c[0]), "+f"(c[1]), "+f"(c[2]), "+f"(c[3])
                 : "r"(a[0]), "r"(a[1]), "r"(a[2]), "r"(a[3]), "r"(b[0]), "r"(b[1]));
}

// MODE 0: emit Ch = fp16(acc + p0[n])
// MODE 2: act = BN(acc); softmax over 64-col groups * att -> Ch (fp16 actn)
template <int MODE>
__global__ __launch_bounds__(256, 2)
void mma_gemm_kernel(const __half* __restrict__ Ah, const __half* __restrict__ Bh,
                     __half* __restrict__ Ch, int M, int N, int K,
                     const float* __restrict__ p0, const float* __restrict__ p1,
                     const float* __restrict__ p2, const float* __restrict__ p3,
                     const float* __restrict__ attp) {
    extern __shared__ __align__(16) unsigned char smem_raw[];
    uint32_t sbase = (uint32_t)__cvta_generic_to_shared(smem_raw);

    const int t = threadIdx.x;
    const int lane = t & 31;
    const int warp = t >> 5;
    const int wy = warp >> 2;
    const int wx = warp & 3;
    const int m0 = blockIdx.y * BM;
    const int n0 = blockIdx.x * BN;

    float acc[4][4][4];
    #pragma unroll
    for (int i = 0; i < 4; i++)
        #pragma unroll
        for (int j = 0; j < 4; j++)
            #pragma unroll
            for (int q = 0; q < 4; q++) acc[i][j][q] = 0.f;

    auto issue = [&](int chunk, int buf) {
        uint32_t sb = sbase + buf * STAGE_B;
        int kpos = chunk * BKK;
        #pragma unroll
        for (int i = 0; i < 4; i++) {
            int c = t + i * 256;
            int row = c >> 3, seg = c & 7;
            uint32_t so = (uint32_t)(row * SSTRIDE + seg * 8) * 2;
            cp16(sb + so, Ah + (size_t)(m0 + row) * K + kpos + seg * 8);
            cp16(sb + MAT_BYTES + so, Bh + (size_t)(n0 + row) * K + kpos + seg * 8);
        }
        asm volatile("cp.async.commit_group;\n");
    };

    const uint32_t aOff = (uint32_t)((wy * 64 + (lane & 15)) * SSTRIDE + ((lane >> 4) * 8)) * 2;
    const uint32_t bOff = (uint32_t)((wx * 32 + ((lane >> 4) * 8) + (lane & 7)) * SSTRIDE
                                     + (((lane >> 3) & 1) * 8)) * 2;

    const int NK = K / BKK;
    issue(0, 0);

    for (int kt = 0; kt < NK; kt++) {
        if (kt + 1 < NK) {
            issue(kt + 1, (kt + 1) & 1);
            asm volatile("cp.async.wait_group 1;\n" ::: "memory");
        } else {
            asm volatile("cp.async.wait_group 0;\n" ::: "memory");
        }
        __syncthreads();
        uint32_t sb = sbase + (kt & 1) * STAGE_B;
        #pragma unroll
        for (int kk = 0; kk < BKK / 16; kk++) {
            uint32_t kby = (uint32_t)(kk * 16) * 2;
            uint32_t ah[4][4], bh[4][2];
            #pragma unroll
            for (int mt = 0; mt < 4; mt++) {
                uint32_t ad = sb + aOff + kby + (uint32_t)(mt * 16 * SSTRIDE) * 2;
                ldsm_x4(ah[mt][0], ah[mt][1], ah[mt][2], ah[mt][3], ad);
            }
            #pragma unroll
            for (int p = 0; p < 2; p++) {
                uint32_t bd = sb + MAT_BYTES + bOff + kby + (uint32_t)(p * 16 * SSTRIDE) * 2;
                uint32_t r0, r1, r2, r3;
                ldsm_x4(r0, r1, r2, r3, bd);
                bh[p * 2][0] = r0; bh[p * 2][1] = r1;
                bh[p * 2 + 1][0] = r2; bh[p * 2 + 1][1] = r3;
            }
            #pragma unroll
            for (int mt = 0; mt < 4; mt++)
                #pragma unroll
                for (int nt = 0; nt < 4; nt++)
                    mma16816(acc[mt][nt], ah[mt], bh[nt]);
        }
        __syncthreads();
    }

    if (MODE == 0) {
        #pragma unroll
        for (int mt = 0; mt < 4; mt++) {
            int r = m0 + wy * 64 + mt * 16 + (lane >> 2);
            #pragma unroll
            for (int nt = 0; nt < 4; nt++) {
                int c = n0 + wx * 32 + nt * 8 + (lane & 3) * 2;
                float v00 = acc[mt][nt][0] + p0[c];
                float v01 = acc[mt][nt][1] + p0[c + 1];
                float v10 = acc[mt][nt][2] + p0[c];
                float v11 = acc[mt][nt][3] + p0[c + 1];
                __half2 hh;
                hh.x = __float2half_rn(v00); hh.y = __float2half_rn(v01);
                *(__half2*)&Ch[(size_t)r * N + c] = hh;
                hh.x = __float2half_rn(v10); hh.y = __float2half_rn(v11);
                *(__half2*)&Ch[(size_t)(r + 8) * N + c] = hh;
            }
        }
    } else {
        // BN in place
        #pragma unroll
        for (int nt = 0; nt < 4; nt++) {
            int c = n0 + wx * 32 + nt * 8 + (lane & 3) * 2;
            float s0 = rsqrtf(p3[c] + BN_EPS) * p0[c];
            float s1 = rsqrtf(p3[c + 1] + BN_EPS) * p0[c + 1];
            float t0 = p1[c] - p2[c] * s0;
            float t1 = p1[c + 1] - p2[c + 1] * s1;
            #pragma unroll
            for (int mt = 0; mt < 4; mt++) {
                acc[mt][nt][0] = acc[mt][nt][0] * s0 + t0;
                acc[mt][nt][1] = acc[mt][nt][1] * s1 + t1;
                acc[mt][nt][2] = acc[mt][nt][2] * s0 + t0;
                acc[mt][nt][3] = acc[mt][nt][3] * s1 + t1;
            }
        }
        float* wm = (float*)smem_raw;           // [128][4]
        float* ws = (float*)smem_raw + 512;     // [128][4]
        // per row-instance warp max
        float gmax[4][2], gsum[4][2];
        #pragma unroll
        for (int mt = 0; mt < 4; mt++)
            #pragma unroll
            for (int q = 0; q < 2; q++) {
                float mx = -1e30f;
                #pragma unroll
                for (int nt = 0; nt < 4; nt++)
                    mx = fmaxf(mx, fmaxf(acc[mt][nt][2 * q], acc[mt][nt][2 * q + 1]));
                mx = fmaxf(mx, __shfl_xor_sync(0xffffffffu, mx, 1));
                mx = fmaxf(mx, __shfl_xor_sync(0xffffffffu, mx, 2));
                gmax[mt][q] = mx;
            }
        __syncthreads();
        if ((lane & 3) == 0) {
            #pragma unroll
            for (int mt = 0; mt < 4; mt++)
                #pragma unroll
                for (int q = 0; q < 2; q++) {
                    int lrow = wy * 64 + mt * 16 + (lane >> 2) + 8 * q;
                    wm[lrow * 4 + wx] = gmax[mt][q];
                }
        }
        __syncthreads();
        #pragma unroll
        for (int mt = 0; mt < 4; mt++)
            #pragma unroll
            for (int q = 0; q < 2; q++) {
                int lrow = wy * 64 + mt * 16 + (lane >> 2) + 8 * q;
                gmax[mt][q] = fmaxf(wm[lrow * 4 + (wx & ~1)], wm[lrow * 4 + (wx | 1)]);
            }
        // exp + sum
        #pragma unroll
        for (int mt = 0; mt < 4; mt++)
            #pragma unroll
            for (int q = 0; q < 2; q++) {
                float s = 0.f;
                #pragma unroll
                for (int nt = 0; nt < 4; nt++) {
                    float e0 = expf(acc[mt][nt][2 * q]     - gmax[mt][q]);
                    float e1 = expf(acc[mt][nt][2 * q + 1] - gmax[mt][q]);
                    acc[mt][nt][2 * q] = e0;
                    acc[mt][nt][2 * q + 1] = e1;
                    s += e0 + e1;
                }
                s += __shfl_xor_sync(0xffffffffu, s, 1);
                s += __shfl_xor_sync(0xffffffffu, s, 2);
                gsum[mt][q] = s;
            }
        __syncthreads();
        if ((lane & 3) == 0) {
            #pragma unroll
            for (int mt = 0; mt < 4; mt++)
                #pragma unroll
                for (int q = 0; q < 2; q++) {
                    int lrow = wy * 64 + mt * 16 + (lane >> 2) + 8 * q;
                    ws[lrow * 4 + wx] = gsum[mt][q];
                }
        }
        __syncthreads();
        int gg = (n0 >> 6) + (wx >> 1);
        #pragma unroll
        for (int mt = 0; mt < 4; mt++)
            #pragma unroll
            for (int q = 0; q < 2; q++) {
                int lrow = wy * 64 + mt * 16 + (lane >> 2) + 8 * q;
                float tot = ws[lrow * 4 + (wx & ~1)] + ws[lrow * 4 + (wx | 1)];
                int rm = m0 + lrow;
                float scl = attp[rm * G_ + gg] / tot;
                #pragma unroll
                for (int nt = 0; nt < 4; nt++) {
                    int c = n0 + wx * 32 + nt * 8 + (lane & 3) * 2;
                    __half2 hh;
                    hh.x = __float2half_rn(acc[mt][nt][2 * q] * scl);
                    hh.y = __float2half_rn(acc[mt][nt][2 * q + 1] * scl);
                    *(__half2*)&Ch[(size_t)rm * N + c] = hh;
                }
            }
    }
}

// ---------------- K7: asum[b,k] from fp16 actn ----------------
__global__ void asum_kernel(const __half* __restrict__ actnh, float* __restrict__ asum) {
    int b = blockIdx.x;
    int t = threadIdx.x;
    int k = t & 63, grp = t >> 6;
    float s = 0.f;
    for (int n = grp; n < N2_; n += 4) {
        int row = b * FR_ + (n >> 3);
        s += __half2float(actnh[(size_t)row * (G_ * K_) + (n & 7) * K_ + k]);
    }
    __shared__ float red[256];
    red[t] = s;
    __syncthreads();
    if (grp == 0) {
        float tot = red[k] + red[64 + k] + red[128 + k] + red[192 + k];
        asum[b * K_ + k] = tot;
    }
}

// ---------------- K8: VLAD via tensor cores ----------------
#define VSTR 72
#define VTILE_B (32 * VSTR * 2)
#define VSTAGE (2 * VTILE_B)
__global__ __launch_bounds__(128)
void vlad_mma_kernel(const __half* __restrict__ hh, const __half* __restrict__ actnh,
                     const float* __restrict__ asum, const float* __restrict__ c2,
                     float* __restrict__ vlad) {
    __shared__ __align__(16) unsigned char smem_raw[2 * VSTAGE];
    uint32_t sbase = (uint32_t)__cvta_generic_to_shared(smem_raw);

    const int b  = blockIdx.x;
    const int f0 = blockIdx.y * 64;
    const int t = threadIdx.x;
    const int lane = t & 31;
    const int w = t >> 5;

    float acc[8][4];
    #pragma unroll
    for (int i = 0; i < 8; i++)
        #pragma unroll
        for (int q = 0; q < 4; q++) acc[i][q] = 0.f;

    auto issue = [&](int chunk, int buf) {
        uint32_t sb = sbase + buf * VSTAGE;
        int n0 = chunk * 32;
        #pragma unroll
        for (int i = 0; i < 2; i++) {
            int c = t + i * 128;
            int row = c >> 3, seg = c & 7;
            int nn = n0 + row;
            int grow = b * FR_ + (nn >> 3);
            uint32_t so = (uint32_t)(row * VSTR + seg * 8) * 2;
            cp16(sb + so, actnh + (size_t)grow * (G_ * K_) + (nn & 7) * K_ + seg * 8);
            cp16(sb + VTILE_B + so, hh + (size_t)grow * ED_ + (nn & 7) * FEAT_ + f0 + seg * 8);
        }
        asm volatile("cp.async.commit_group;\n");
    };

    const int NK = N2_ / 32;
    issue(0, 0);

    int i8 = lane & 7, quad = lane >> 3;
    uint32_t aRow = (uint32_t)((quad >> 1) * 8 + i8);
    uint32_t aCol = (uint32_t)(16 * w + (quad & 1) * 8);
    uint32_t bRow = (uint32_t)((quad & 1) * 8 + i8);
    uint32_t bCol0 = (uint32_t)((quad >> 1) * 8);

    for (int kt = 0; kt < NK; kt++) {
        if (kt + 1 < NK) {
            issue(kt + 1, (kt + 1) & 1);
            asm volatile("cp.async.wait_group 1;\n" ::: "memory");
        } else {
            asm volatile("cp.async.wait_group 0;\n" ::: "memory");
        }
        __syncthreads();
        uint32_t sb = sbase + (kt & 1) * VSTAGE;
        #pragma unroll
        for (int kk = 0; kk < 2; kk++) {
            uint32_t nbase = (uint32_t)(kk * 16);
            uint32_t aF[4];
            ldsm_x4t(aF[0], aF[1], aF[2], aF[3],
                     sb + ((nbase + aRow) * VSTR + aCol) * 2);
            uint32_t bF[8][2];
            #pragma unroll
            for (int fp = 0; fp < 4; fp++) {
                uint32_t r0, r1, r2, r3;
                ldsm_x4t(r0, r1, r2, r3,
                         sb + VTILE_B + ((nbase + bRow) * VSTR + fp * 16 + bCol0) * 2);
                bF[fp * 2][0] = r0;     bF[fp * 2][1] = r1;
                bF[fp * 2 + 1][0] = r2; bF[fp * 2 + 1][1] = r3;
            }
            #pragma unroll
            for (int nt = 0; nt < 8; nt++)
                mma16816(acc[nt], aF, bF[nt]);
        }
        __syncthreads();
    }

    int k1 = 16 * w + (lane >> 2);
    int k2 = k1 + 8;
    float a1 = asum[b * K_ + k1];
    float a2 = asum[b * K_ + k2];
    #pragma unroll
    for (int nt = 0; nt < 8; nt++) {
        int f = f0 + nt * 8 + (lane & 3) * 2;
        float* o1 = &vlad[((size_t)b * FEAT_ + f) * K_];
        o1[k1]        = acc[nt][0] - a1 * c2[(size_t)f * K_ + k1];
        o1[K_ + k1]   = acc[nt][1] - a1 * c2[(size_t)(f + 1) * K_ + k1];
        o1[k2]        = acc[nt][2] - a2 * c2[(size_t)f * K_ + k2];
        o1[K_ + k2]   = acc[nt][3] - a2 * c2[(size_t)(f + 1) * K_ + k2];
    }
}

// ---------------- K9: intra-norm + BN2 ----------------
__global__ void intranorm_bn_kernel(const float* __restrict__ vlad, float* __restrict__ vladn,
                                    const float* __restrict__ g, const float* __restrict__ bb,
                                    const float* __restrict__ mm, const float* __restrict__ vv) {
    int b = blockIdx.x;
    int t = threadIdx.x;
    int k = t & 63, fg = t >> 6;
    float s = 0.f;
    for (int f = fg; f < FEAT_; f += 8) {
        float x = vlad[((size_t)b * FEAT_ + f) * K_ + k];
        s += x * x;
    }
    __shared__ float red[512];
    red[t] = s;
    __syncthreads();
    if (fg == 0) {
        float tot = 0.f;
        #pragma unroll
        for (int i = 0; i < 8; i++) tot += red[i * 64 + k];
        red[k] = 1.f / fmaxf(sqrtf(tot), L2_EPS);
    }
    __syncthreads();
    float inv = red[k];
    for (int f = fg; f < FEAT_; f += 8) {
        int idx = f * K_ + k;
        float x = vlad[((size_t)b * FEAT_ + f) * K_ + k] * inv;
        vladn[(size_t)b * VLAD_ + idx] =
            (x - mm[idx]) * rsqrtf(vv[idx] + BN_EPS) * g[idx] + bb[idx];
    }
}

// ---------------- K10: broadcast bias init ----------------
__global__ void bias_init_kernel(float* __restrict__ C, const float* __restrict__ bias,
                                 int rows, int N) {
    int idx = blockIdx.x * blockDim.x + threadIdx.x;
    if (idx < rows * N) C[idx] = bias[idx % N];
}

// ---------------- K11: skinny GEMM (split-K, atomic) ----------------
__global__ void skinny32_kernel(const float* __restrict__ A, const float* __restrict__ W,
                                float* __restrict__ C, int N, int K, int KC) {
    int o0 = blockIdx.x * 128;
    int k0 = blockIdx.y * KC;
    __shared__ float As[32][36];
    __shared__ float Ws[32][132];
    int t = threadIdx.x;
    int kl = t & 31, rg = t >> 5;
    int oq = t & 31, bq = t >> 5;
    float acc[4][4];
    #pragma unroll
    for (int i = 0; i < 4; i++)
        #pragma unroll
        for (int j = 0; j < 4; j++) acc[i][j] = 0.f;

    int kend = min(k0 + KC, K);
    for (int kt = k0; kt < kend; kt += 32) {
        __syncthreads();
        #pragma unroll
        for (int i = 0; i < 4; i++) {
            int b = rg + i * 8;
            As[kl][b] = A[(size_t)b * K + kt + kl];
        }
        #pragma unroll
        for (int i = 0; i < 16; i++) {
            int o = rg + i * 8;
            int og = o0 + o;
            Ws[kl][o] = (og < N) ? W[(size_t)og * K + kt + kl] : 0.f;
        }
        __syncthreads();
        #pragma unroll
        for (int kk = 0; kk < 32; kk++) {
            float4 w4 = *(const float4*)&Ws[kk][oq * 4];
            float4 a4 = *(const float4*)&As[kk][bq * 4];
            float av[4] = {a4.x, a4.y, a4.z, a4.w};
            float wv[4] = {w4.x, w4.y, w4.z, w4.w};
            #pragma unroll
            for (int i = 0; i < 4; i++)
                #pragma unroll
                for (int j = 0; j < 4; j++) acc[i][j] += av[i] * wv[j];
        }
    }
    #pragma unroll
    for (int i = 0; i < 4; i++) {
        int b = bq * 4 + i;
        #pragma unroll
        for (int j = 0; j < 4; j++) {
            int o = o0 + oq * 4 + j;
            if (o < N) atomicAdd(&C[(size_t)b * N + o], acc[i][j]);
        }
    }
}

// ---------------- K12: BN ----------------
__global__ void bn_kernel(const float* __restrict__ in, float* __restrict__ out,
                          const float* __restrict__ g, const float* __restrict__ bb,
                          const float* __restrict__ mm, const float* __restrict__ vv,
                          int rows, int N) {
    int idx = blockIdx.x * blockDim.x + threadIdx.x;
    if (idx < rows * N) {
        int c = idx % N;
        out[idx] = (in[idx] - mm[c]) * rsqrtf(vv[c] + BN_EPS) * g[c] + bb[c];
    }
}

// ---------------- K13/K14: SE gating ----------------
__global__ void se1_kernel(const float* __restrict__ y, const float* __restrict__ w,
                           const float* __restrict__ bias,
                           const float* __restrict__ g, const float* __restrict__ bb,
                           const float* __restrict__ mm, const float* __restrict__ vv,
                           float* __restrict__ z) {
    int warp = threadIdx.x >> 5, lane = threadIdx.x & 31;
    int idx = blockIdx.x * 8 + warp;
    int b = idx / HR_, o = idx % HR_;
    const float* yr = y + (size_t)b * H_;
    const float* wr = w + (size_t)o * H_;
    float s = 0.f;
    for (int k = lane; k < H_; k += 32) s += yr[k] * wr[k];
    for (int off = 16; off; off >>= 1) s += __shfl_xor_sync(0xffffffffu, s, off);
    if (lane == 0) {
        float v = s + bias[o];
        v = (v - mm[o]) * rsqrtf(vv[o] + BN_EPS) * g[o] + bb[o];
        z[(size_t)b * HR_ + o] = fmaxf(v, 0.f);
    }
}

__global__ void se2_kernel(const float* __restrict__ z, const float* __restrict__ w,
                           const float* __restrict__ bias, const float* __restrict__ y,
                           float* __restrict__ yg) {
    int warp = threadIdx.x >> 5, lane = threadIdx.x & 31;
    int idx = blockIdx.x * 8 + warp;
    int b = idx / H_, o = idx % H_;
    const float* zr = z + (size_t)b * HR_;
    const float* wr = w + (size_t)o * HR_;
    float s = 0.f;
    for (int k = lane; k < HR_; k += 32) s += zr[k] * wr[k];
    for (int off = 16; off; off >>= 1) s += __shfl_xor_sync(0xffffffffu, s, off);
    if (lane == 0) {
        float gate = 1.f / (1.f + expf(-(s + bias[o])));
        yg[(size_t)b * H_ + o] = y[(size_t)b * H_ + o] * gate;
    }
}

// ---------------- host launcher ----------------
extern "C" void kernel_launch(void* const* d_in, const int* in_sizes, int n_in,
                              void* d_out, int out_size) {
    const float* x     = (const float*)d_in[0];
    const float* fc1_w = (const float*)d_in[1];
    const float* fc1_b = (const float*)d_in[2];
    const float* fc2_w = (const float*)d_in[3];
    const float* fc2_b = (const float*)d_in[4];
    const float* c1    = (const float*)d_in[5];
    const float* c2    = (const float*)d_in[6];
    const float* bn1_g = (const float*)d_in[7];
    const float* bn1_b = (const float*)d_in[8];
    const float* bn1_m = (const float*)d_in[9];
    const float* bn1_v = (const float*)d_in[10];
    const float* bn2_g = (const float*)d_in[11];
    const float* bn2_b = (const float*)d_in[12];
    const float* bn2_m = (const float*)d_in[13];
    const float* bn2_v = (const float*)d_in[14];
    const float* cgf_w = (const float*)d_in[15];
    const float* cgf_b = (const float*)d_in[16];
    const float* cgbn_g = (const float*)d_in[17];
    const float* cgbn_b = (const float*)d_in[18];
    const float* cgbn_m = (const float*)d_in[19];
    const float* cgbn_v = (const float*)d_in[20];
    const float* g1_w  = (const float*)d_in[21];
    const float* g1_b  = (const float*)d_in[22];
    const float* gbn_g = (const float*)d_in[23];
    const float* gbn_b = (const float*)d_in[24];
    const float* gbn_m = (const float*)d_in[25];
    const float* gbn_v = (const float*)d_in[26];
    const float* g2_w  = (const float*)d_in[27];
    const float* g2_b  = (const float*)d_in[28];
    const float* fc3_w = (const float*)d_in[29];
    const float* fc3_b = (const float*)d_in[30];
    float* out = (float*)d_out;

    float *att, *asum, *vlad, *vladn, *y0, *y, *z, *yg, *w2e, *attb;
    __half *xh, *wh, *hh, *c1h, *actnh;
    cudaGetSymbolAddress((void**)&att,   g_att);
    cudaGetSymbolAddress((void**)&asum,  g_asum);
    cudaGetSymbolAddress((void**)&vlad,  g_vlad);
    cudaGetSymbolAddress((void**)&vladn, g_vladn);
    cudaGetSymbolAddress((void**)&y0,    g_y0);
    cudaGetSymbolAddress((void**)&y,     g_y);
    cudaGetSymbolAddress((void**)&z,     g_z);
    cudaGetSymbolAddress((void**)&yg,    g_yg);
    cudaGetSymbolAddress((void**)&w2e,   g_w2e);
    cudaGetSymbolAddress((void**)&attb,  g_attb);
    cudaGetSymbolAddress((void**)&xh,    g_xh);
    cudaGetSymbolAddress((void**)&wh,    g_wh);
    cudaGetSymbolAddress((void**)&hh,    g_hh);
    cudaGetSymbolAddress((void**)&c1h,   g_c1h);
    cudaGetSymbolAddress((void**)&actnh, g_actnh);

    cudaFuncSetAttribute((const void*)mma_gemm_kernel<0>,
                         cudaFuncAttributeMaxDynamicSharedMemorySize, GEMM_SMEM);
    cudaFuncSetAttribute((const void*)mma_gemm_kernel<2>,
                         cudaFuncAttributeMaxDynamicSharedMemorySize, GEMM_SMEM);

    // launch 1-3: fused attention weights
    zero_kernel<<<(G_ * D_ + 255) / 256, 256>>>(w2e, G_ * D_);
    fuse_attw_kernel<<<dim3(D_ / 256, ED_ / 256), 256>>>(fc1_w, fc2_w, w2e);
    fuse_attb_kernel<<<1, 256>>>(fc2_w, fc1_b, fc2_b, attb);

    // launch 4: fc1_w -> fp16
    tohalf_kernel<<<(ED_ * D_ / 4 + 255) / 256, 256>>>(fc1_w, wh, ED_ * D_);

    // launch 5: rownorm + x->fp16 + attention (fused)
    rownorm_att_kernel<<<M_, 256>>>(x, w2e, attb, xh, att);

    // launch 6 (ncu target): h = xn @ fc1_w^T + fc1_b — fp16 MMA
    mma_gemm_kernel<0><<<dim3(ED_ / BN, M_ / BM), 256, GEMM_SMEM>>>(
        xh, wh, hh, M_, ED_, D_, fc1_b, nullptr, nullptr, nullptr, nullptr);

    // launch 7: c1^T -> fp16
    transpose_half_kernel<<<dim3((G_ * K_) / 32, ED_ / 32), 256>>>(c1, c1h, ED_, G_ * K_);

    // launch 8: actn = softmax(BN1(h @ c1)) * att — fused epilogue
    mma_gemm_kernel<2><<<dim3((G_ * K_) / BN, M_ / BM), 256, GEMM_SMEM>>>(
        hh, c1h, actnh, M_, G_ * K_, ED_, bn1_g, bn1_b, bn1_m, bn1_v, att);

    // launch 9: asum
    asum_kernel<<<B_, 256>>>(actnh, asum);

    // launch 10: vlad — tensor cores
    vlad_mma_kernel<<<dim3(B_, FEAT_ / 64), 128>>>(hh, actnh, asum, c2, vlad);

    // launch 11: intra-norm + BN2
    intranorm_bn_kernel<<<B_, 512>>>(vlad, vladn, bn2_g, bn2_b, bn2_m, bn2_v);

    // launch 12-14: y = BN(vladn @ cgf_w^T + cgf_b) — 64-way split-K
    bias_init_kernel<<<(B_ * H_ + 255) / 256, 256>>>(y0, cgf_b, B_, H_);
    skinny32_kernel<<<dim3(H_ / 128, 64), 256>>>(vladn, cgf_w, y0, H_, VLAD_, VLAD_ / 64);
    bn_kernel<<<(B_ * H_ + 255) / 256, 256>>>(y0, y, cgbn_g, cgbn_b, cgbn_m, cgbn_v, B_, H_);

    // launch 15-16: SE gating
    se1_kernel<<<(B_ * HR_) / 8, 256>>>(y, g1_w, g1_b, gbn_g, gbn_b, gbn_m, gbn_v, z);
    se2_kernel<<<(B_ * H_) / 8, 256>>>(z, g2_w, g2_b, y, yg);

    // launch 17-18: out = yg @ fc3_w^T + fc3_b — 16-way split-K
    bias_init_kernel<<<(B_ * NC_ + 255) / 256, 256>>>(out, fc3_b, B_, NC_);
    skinny32_kernel<<<dim3((NC_ + 127) / 128, 16), 256>>>(yg, fc3_w, out, NC_, H_, H_ / 16);
}

// round 16
// speedup vs baseline: 1.1433x; 1.1433x over previous
#include <cuda_runtime.h>
#include <cuda_fp16.h>
#include <math.h>
#include <stdint.h>

// ---------------- problem constants ----------------
#define B_    32
#define FR_   300
#define D_    2048
#define ED_   4096      // E*D
#define G_    8
#define K_    64
#define FEAT_ 512       // E*D/G
#define VLAD_ 32768     // K*FEAT
#define H_    2048
#define HR_   256       // H/R
#define NC_   3862
#define M_    (B_*FR_)  // 9600
#define N2_   2400      // FR*G
#define BN_EPS 1e-5f
#define L2_EPS 1e-12f

// ---------------- scratch (device globals; no allocs allowed) ----------------
__device__ __align__(128) float g_att[M_ * G_];
__device__ __align__(128) float g_act[M_ * (G_*K_)];
__device__ __align__(128) float g_asum[B_ * K_];
__device__ __align__(128) float g_vlad[B_ * FEAT_ * K_];
__device__ __align__(128) float g_vladn[B_ * VLAD_];
__device__ __align__(128) float g_y0[B_ * H_];
__device__ __align__(128) float g_y[B_ * H_];
__device__ __align__(128) float g_z[B_ * HR_];
__device__ __align__(128) float g_yg[B_ * H_];
__device__ __align__(128) float g_w2e[G_ * D_];
__device__ __align__(128) float g_attb[G_];
// fp16 buffers
__device__ __align__(128) __half g_xh[M_ * D_];
__device__ __align__(128) __half g_wh[ED_ * D_];
__device__ __align__(128) __half g_hh[M_ * ED_];
__device__ __align__(128) __half g_c1h[(G_*K_) * ED_];
__device__ __align__(128) __half g_actnh[M_ * (G_*K_)];

// ---------------- K1: fused rownorm + x->fp16 + attention ----------------
__global__ void rownorm_att_kernel(const float* __restrict__ x,
                                   const float* __restrict__ w2e,
                                   const float* __restrict__ attb,
                                   __half* __restrict__ xh, float* __restrict__ att) {
    __shared__ float sx[D_];
    __shared__ float red[8];
    __shared__ float sinv;
    int m = blockIdx.x;
    int t = threadIdx.x;                 // 256 threads
    const float* row = x + (size_t)m * D_;
    float4 v0 = *(const float4*)(row + t * 4);
    float4 v1 = *(const float4*)(row + 1024 + t * 4);
    float s = v0.x * v0.x + v0.y * v0.y + v0.z * v0.z + v0.w * v0.w
            + v1.x * v1.x + v1.y * v1.y + v1.z * v1.z + v1.w * v1.w;
    for (int o = 16; o; o >>= 1) s += __shfl_xor_sync(0xffffffffu, s, o);
    if ((t & 31) == 0) red[t >> 5] = s;
    __syncthreads();
    if (t == 0) {
        float tot = 0.f;
        #pragma unroll
        for (int i = 0; i < 8; i++) tot += red[i];
        sinv = 1.f / fmaxf(sqrtf(tot), L2_EPS);
    }
    __syncthreads();
    float inv = sinv;
    v0.x *= inv; v0.y *= inv; v0.z *= inv; v0.w *= inv;
    v1.x *= inv; v1.y *= inv; v1.z *= inv; v1.w *= inv;
    *(float4*)&sx[t * 4] = v0;
    *(float4*)&sx[1024 + t * 4] = v1;
    __half* dst = xh + (size_t)m * D_;
    __half2 a;
    a.x = __float2half_rn(v0.x); a.y = __float2half_rn(v0.y);
    *(__half2*)&dst[t * 4] = a;
    a.x = __float2half_rn(v0.z); a.y = __float2half_rn(v0.w);
    *(__half2*)&dst[t * 4 + 2] = a;
    a.x = __float2half_rn(v1.x); a.y = __float2half_rn(v1.y);
    *(__half2*)&dst[1024 + t * 4] = a;
    a.x = __float2half_rn(v1.z); a.y = __float2half_rn(v1.w);
    *(__half2*)&dst[1024 + t * 4 + 2] = a;
    __syncthreads();
    int g = t >> 5, lane = t & 31;
    const float* wr = w2e + (size_t)g * D_;
    float sa = 0.f;
    for (int k = lane * 2; k < D_; k += 64) {
        float2 w = *(const float2*)&wr[k];
        sa += sx[k] * w.x + sx[k + 1] * w.y;
    }
    for (int o = 16; o; o >>= 1) sa += __shfl_xor_sync(0xffffffffu, sa, o);
    if (lane == 0) {
        float v = sa + attb[g];
        att[m * G_ + g] = 1.f / (1.f + expf(-v));
    }
}

// ---------------- K2: fp32 -> fp16 ----------------
__global__ void tohalf_kernel(const float* __restrict__ src, __half* __restrict__ dst, int n) {
    int i = (blockIdx.x * blockDim.x + threadIdx.x) * 4;
    if (i >= n) return;
    float4 v = *(const float4*)(src + i);
    __half2 a; a.x = __float2half_rn(v.x); a.y = __float2half_rn(v.y);
    __half2 b; b.x = __float2half_rn(v.z); b.y = __float2half_rn(v.w);
    *(__half2*)&dst[i]     = a;
    *(__half2*)&dst[i + 2] = b;
}

// ---------------- K2b: fused transpose -> fp16: c1[R,C] -> c1h[C,R] ----------------
__global__ void transpose_half_kernel(const float* __restrict__ in,
                                      __half* __restrict__ outh, int R, int C) {
    __shared__ float tile[32][33];
    int c0 = blockIdx.x * 32, r0 = blockIdx.y * 32;
    int tx = threadIdx.x & 31, ty = threadIdx.x >> 5;
    #pragma unroll
    for (int i = 0; i < 32; i += 8)
        tile[ty + i][tx] = in[(size_t)(r0 + ty + i) * C + c0 + tx];
    __syncthreads();
    #pragma unroll
    for (int i = 0; i < 32; i += 8) {
        float v = tile[tx][ty + i];
        outh[(size_t)(c0 + ty + i) * R + r0 + tx] = __float2half_rn(v);
    }
}

// ---------------- zero ----------------
__global__ void zero_kernel(float* __restrict__ p, int n) {
    int i = blockIdx.x * blockDim.x + threadIdx.x;
    if (i < n) p[i] = 0.f;
}

// ---------------- K2c: w2e[g][d] += sum_{e in chunk} fc2_w[g][e] * fc1_w[e][d] --------
__global__ void fuse_attw_kernel(const float* __restrict__ fc1_w,
                                 const float* __restrict__ fc2_w,
                                 float* __restrict__ w2e) {
    __shared__ float f2[G_][256];
    int d = blockIdx.x * 256 + threadIdx.x;
    int e0 = blockIdx.y * 256;
    #pragma unroll
    for (int g = 0; g < G_; g++)
        f2[g][threadIdx.x] = fc2_w[(size_t)g * ED_ + e0 + threadIdx.x];
    __syncthreads();
    float acc[G_];
    #pragma unroll
    for (int g = 0; g < G_; g++) acc[g] = 0.f;
    for (int e = 0; e < 256; e++) {
        float w1 = fc1_w[(size_t)(e0 + e) * D_ + d];
        #pragma unroll
        for (int g = 0; g < G_; g++) acc[g] += f2[g][e] * w1;
    }
    #pragma unroll
    for (int g = 0; g < G_; g++) atomicAdd(&w2e[(size_t)g * D_ + d], acc[g]);
}

// ---------------- K2d: attb[g] = fc2_b[g] + dot(fc2_w[g], fc1_b) ----------------
__global__ void fuse_attb_kernel(const float* __restrict__ fc2_w,
                                 const float* __restrict__ fc1_b,
                                 const float* __restrict__ fc2_b,
                                 float* __restrict__ attb) {
    int g = threadIdx.x >> 5, lane = threadIdx.x & 31;
    const float* wr = fc2_w + (size_t)g * ED_;
    float s = 0.f;
    for (int k = lane; k < ED_; k += 32) s += wr[k] * fc1_b[k];
    for (int o = 16; o; o >>= 1) s += __shfl_xor_sync(0xffffffffu, s, o);
    if (lane == 0) attb[g] = s + fc2_b[g];
}

// ---------------- tensor-core GEMM: C[M,N] = A[M,K] * B[N,K]^T  (fp16 1-pass) ---------
#define BM 128
#define BN 128
#define BKK 64
#define SSTRIDE 72
#define MAT_BYTES (128 * SSTRIDE * 2)     // 18432
#define STAGE_B (2 * MAT_BYTES)           // 36864
#define GEMM_SMEM (2 * STAGE_B)           // 73728

__device__ __forceinline__ void cp16(uint32_t dst, const void* src) {
    asm volatile("cp.async.cg.shared.global [%0], [%1], 16;\n" :: "r"(dst), "l"(src));
}
__device__ __forceinline__ void ldsm_x4(uint32_t& r0, uint32_t& r1, uint32_t& r2, uint32_t& r3,
                                        uint32_t addr) {
    asm volatile("ldmatrix.sync.aligned.m8n8.x4.shared.b16 {%0,%1,%2,%3}, [%4];\n"
                 : "=r"(r0), "=r"(r1), "=r"(r2), "=r"(r3) : "r"(addr));
}
__device__ __forceinline__ void ldsm_x4t(uint32_t& r0, uint32_t& r1, uint32_t& r2, uint32_t& r3,
                                         uint32_t addr) {
    asm volatile("ldmatrix.sync.aligned.m8n8.x4.trans.shared.b16 {%0,%1,%2,%3}, [%4];\n"
                 : "=r"(r0), "=r"(r1), "=r"(r2), "=r"(r3) : "r"(addr));
}
__device__ __forceinline__ void mma16816(float* c, const uint32_t* a, const uint32_t* b) {
    asm volatile("mma.sync.aligned.m16n8k16.row.col.f32.f16.f16.f32 "
                 "{%0,%1,%2,%3},{%4,%5,%6,%7},{%8,%9},{%0,%1,%2,%3};\n"
                 : "+f"(c[0]), "+f"(c[1]), "+f"(c[2]), "+f"(c[3])
                 : "r"(a[0]), "r"(a[1]), "r"(a[2]), "r"(a[3]), "r"(b[0]), "r"(b[1]));
}

// MODE 0: emit Ch = fp16(acc + p0[n])
// MODE 1: emit C fp32 = (acc - p2[n])*rsqrt(p3[n]+eps)*p0[n] + p1[n]
template <int MODE>
__global__ __launch_bounds__(256, 2)
void mma_gemm_kernel(const __half* __restrict__ Ah, const __half* __restrict__ Bh,
                     float* __restrict__ C, __half* __restrict__ Ch,
                     int M, int N, int K,
                     const float* __restrict__ p0, const float* __restrict__ p1,
                     const float* __restrict__ p2, const float* __restrict__ p3) {
    extern __shared__ __align__(16) unsigned char smem_raw[];
    uint32_t sbase = (uint32_t)__cvta_generic_to_shared(smem_raw);

    const int t = threadIdx.x;
    const int lane = t & 31;
    const int warp = t >> 5;
    const int wy = warp >> 2;
    const int wx = warp & 3;
    const int m0 = blockIdx.y * BM;
    const int n0 = blockIdx.x * BN;

    float acc[4][4][4];
    #pragma unroll
    for (int i = 0; i < 4; i++)
        #pragma unroll
        for (int j = 0; j < 4; j++)
            #pragma unroll
            for (int q = 0; q < 4; q++) acc[i][j][q] = 0.f;

    auto issue = [&](int chunk, int buf) {
        uint32_t sb = sbase + buf * STAGE_B;
        int kpos = chunk * BKK;
        #pragma unroll
        for (int i = 0; i < 4; i++) {
            int c = t + i * 256;
            int row = c >> 3, seg = c & 7;
            uint32_t so = (uint32_t)(row * SSTRIDE + seg * 8) * 2;
            cp16(sb + so, Ah + (size_t)(m0 + row) * K + kpos + seg * 8);
            cp16(sb + MAT_BYTES + so, Bh + (size_t)(n0 + row) * K + kpos + seg * 8);
        }
        asm volatile("cp.async.commit_group;\n");
    };

    const uint32_t aOff = (uint32_t)((wy * 64 + (lane & 15)) * SSTRIDE + ((lane >> 4) * 8)) * 2;
    const uint32_t bOff = (uint32_t)((wx * 32 + ((lane >> 4) * 8) + (lane & 7)) * SSTRIDE
                                     + (((lane >> 3) & 1) * 8)) * 2;

    const int NK = K / BKK;
    issue(0, 0);

    for (int kt = 0; kt < NK; kt++) {
        if (kt + 1 < NK) {
            issue(kt + 1, (kt + 1) & 1);
            asm volatile("cp.async.wait_group 1;\n" ::: "memory");
        } else {
            asm volatile("cp.async.wait_group 0;\n" ::: "memory");
        }
        __syncthreads();
        uint32_t sb = sbase + (kt & 1) * STAGE_B;
        #pragma unroll
        for (int kk = 0; kk < BKK / 16; kk++) {
            uint32_t kby = (uint32_t)(kk * 16) * 2;
            uint32_t ah[4][4], bh[4][2];
            #pragma unroll
            for (int mt = 0; mt < 4; mt++) {
                uint32_t ad = sb + aOff + kby + (uint32_t)(mt * 16 * SSTRIDE) * 2;
                ldsm_x4(ah[mt][0], ah[mt][1], ah[mt][2], ah[mt][3], ad);
            }
            #pragma unroll
            for (int p = 0; p < 2; p++) {
                uint32_t bd = sb + MAT_BYTES + bOff + kby + (uint32_t)(p * 16 * SSTRIDE) * 2;
                uint32_t r0, r1, r2, r3;
                ldsm_x4(r0, r1, r2, r3, bd);
                bh[p * 2][0] = r0; bh[p * 2][1] = r1;
                bh[p * 2 + 1][0] = r2; bh[p * 2 + 1][1] = r3;
            }
            #pragma unroll
            for (int mt = 0; mt < 4; mt++)
                #pragma unroll
                for (int nt = 0; nt < 4; nt++)
                    mma16816(acc[mt][nt], ah[mt], bh[nt]);
        }
        __syncthreads();
    }

    #pragma unroll
    for (int mt = 0; mt < 4; mt++) {
        int r = m0 + wy * 64 + mt * 16 + (lane >> 2);
        #pragma unroll
        for (int nt = 0; nt < 4; nt++) {
            int c = n0 + wx * 32 + nt * 8 + (lane & 3) * 2;
            float v00 = acc[mt][nt][0], v01 = acc[mt][nt][1];
            float v10 = acc[mt][nt][2], v11 = acc[mt][nt][3];
            if (MODE == 0) {
                float b0 = p0[c], b1 = p0[c + 1];
                v00 += b0; v01 += b1; v10 += b0; v11 += b1;
                __half2 hh;
                hh.x = __float2half_rn(v00); hh.y = __float2half_rn(v01);
                *(__half2*)&Ch[(size_t)r * N + c] = hh;
                hh.x = __float2half_rn(v10); hh.y = __float2half_rn(v11);
                *(__half2*)&Ch[(size_t)(r + 8) * N + c] = hh;
            } else {
                float s0 = rsqrtf(p3[c] + BN_EPS) * p0[c];
                float s1 = rsqrtf(p3[c + 1] + BN_EPS) * p0[c + 1];
                float t0 = p1[c] - p2[c] * s0;
                float t1 = p1[c + 1] - p2[c + 1] * s1;
                float2 o0 = {v00 * s0 + t0, v01 * s1 + t1};
                float2 o1 = {v10 * s0 + t0, v11 * s1 + t1};
                *(float2*)&C[(size_t)r * N + c] = o0;
                *(float2*)&C[(size_t)(r + 8) * N + c] = o1;
            }
        }
    }
}

// ---------------- K6: softmax * att -> fp16 actn, with fused asum --------------------
__global__ void softmax_att_kernel(const float* __restrict__ act, const float* __restrict__ att,
                                   __half* __restrict__ actnh, float* __restrict__ asum) {
    __shared__ float red[G_][64];
    int m = blockIdx.x;
    int g = threadIdx.x >> 5, lane = threadIdx.x & 31;
    const float* row = act + (size_t)m * (G_ * K_) + g * K_;
    float v0 = row[lane], v1 = row[lane + 32];
    float mx = fmaxf(v0, v1);
    for (int o = 16; o; o >>= 1) mx = fmaxf(mx, __shfl_xor_sync(0xffffffffu, mx, o));
    float e0 = expf(v0 - mx), e1 = expf(v1 - mx);
    float s = e0 + e1;
    for (int o = 16; o; o >>= 1) s += __shfl_xor_sync(0xffffffffu, s, o);
    float scl = att[m * G_ + g] / s;
    float a0 = e0 * scl, a1 = e1 * scl;
    __half* orow = actnh + (size_t)m * (G_ * K_) + g * K_;
    orow[lane] = __float2half_rn(a0);
    orow[lane + 32] = __float2half_rn(a1);
    red[g][lane] = a0;
    red[g][lane + 32] = a1;
    __syncthreads();
    int t = threadIdx.x;
    if (t < 64) {
        float tot = 0.f;
        #pragma unroll
        for (int gg = 0; gg < G_; gg++) tot += red[gg][t];
        atomicAdd(&asum[(m / FR_) * K_ + t], tot);
    }
}

// ---------------- K8: VLAD via tensor cores ----------------
#define VSTR 72
#define VTILE_B (32 * VSTR * 2)
#define VSTAGE (2 * VTILE_B)
__global__ __launch_bounds__(128)
void vlad_mma_kernel(const __half* __restrict__ hh, const __half* __restrict__ actnh,
                     const float* __restrict__ asum, const float* __restrict__ c2,
                     float* __restrict__ vlad) {
    __shared__ __align__(16) unsigned char smem_raw[2 * VSTAGE];
    uint32_t sbase = (uint32_t)__cvta_generic_to_shared(smem_raw);

    const int b  = blockIdx.x;
    const int f0 = blockIdx.y * 64;
    const int t = threadIdx.x;
    const int lane = t & 31;
    const int w = t >> 5;

    float acc[8][4];
    #pragma unroll
    for (int i = 0; i < 8; i++)
        #pragma unroll
        for (int q = 0; q < 4; q++) acc[i][q] = 0.f;

    auto issue = [&](int chunk, int buf) {
        uint32_t sb = sbase + buf * VSTAGE;
        int n0 = chunk * 32;
        #pragma unroll
        for (int i = 0; i < 2; i++) {
            int c = t + i * 128;
            int row = c >> 3, seg = c & 7;
            int nn = n0 + row;
            int grow = b * FR_ + (nn >> 3);
            uint32_t so = (uint32_t)(row * VSTR + seg * 8) * 2;
            cp16(sb + so, actnh + (size_t)grow * (G_ * K_) + (nn & 7) * K_ + seg * 8);
            cp16(sb + VTILE_B + so, hh + (size_t)grow * ED_ + (nn & 7) * FEAT_ + f0 + seg * 8);
        }
        asm volatile("cp.async.commit_group;\n");
    };

    const int NK = N2_ / 32;
    issue(0, 0);

    int i8 = lane & 7, quad = lane >> 3;
    uint32_t aRow = (uint32_t)((quad >> 1) * 8 + i8);
    uint32_t aCol = (uint32_t)(16 * w + (quad & 1) * 8);
    uint32_t bRow = (uint32_t)((quad & 1) * 8 + i8);
    uint32_t bCol0 = (uint32_t)((quad >> 1) * 8);

    for (int kt = 0; kt < NK; kt++) {
        if (kt + 1 < NK) {
            issue(kt + 1, (kt + 1) & 1);
            asm volatile("cp.async.wait_group 1;\n" ::: "memory");
        } else {
            asm volatile("cp.async.wait_group 0;\n" ::: "memory");
        }
        __syncthreads();
        uint32_t sb = sbase + (kt & 1) * VSTAGE;
        #pragma unroll
        for (int kk = 0; kk < 2; kk++) {
            uint32_t nbase = (uint32_t)(kk * 16);
            uint32_t aF[4];
            ldsm_x4t(aF[0], aF[1], aF[2], aF[3],
                     sb + ((nbase + aRow) * VSTR + aCol) * 2);
            uint32_t bF[8][2];
            #pragma unroll
            for (int fp = 0; fp < 4; fp++) {
                uint32_t r0, r1, r2, r3;
                ldsm_x4t(r0, r1, r2, r3,
                         sb + VTILE_B + ((nbase + bRow) * VSTR + fp * 16 + bCol0) * 2);
                bF[fp * 2][0] = r0;     bF[fp * 2][1] = r1;
                bF[fp * 2 + 1][0] = r2; bF[fp * 2 + 1][1] = r3;
            }
            #pragma unroll
            for (int nt = 0; nt < 8; nt++)
                mma16816(acc[nt], aF, bF[nt]);
        }
        __syncthreads();
    }

    int k1 = 16 * w + (lane >> 2);
    int k2 = k1 + 8;
    float a1 = asum[b * K_ + k1];
    float a2 = asum[b * K_ + k2];
    #pragma unroll
    for (int nt = 0; nt < 8; nt++) {
        int f = f0 + nt * 8 + (lane & 3) * 2;
        float* o1 = &vlad[((size_t)b * FEAT_ + f) * K_];
        o1[k1]        = acc[nt][0] - a1 * c2[(size_t)f * K_ + k1];
        o1[K_ + k1]   = acc[nt][1] - a1 * c2[(size_t)(f + 1) * K_ + k1];
        o1[k2]        = acc[nt][2] - a2 * c2[(size_t)f * K_ + k2];
        o1[K_ + k2]   = acc[nt][3] - a2 * c2[(size_t)(f + 1) * K_ + k2];
    }
}

// ---------------- K9: intra-norm + BN2 ----------------
__global__ void intranorm_bn_kernel(const float* __restrict__ vlad, float* __restrict__ vladn,
                                    const float* __restrict__ g, const float* __restrict__ bb,
                                    const float* __restrict__ mm, const float* __restrict__ vv) {
    int b = blockIdx.x;
    int t = threadIdx.x;
    int k = t & 63, fg = t >> 6;
    float s = 0.f;
    for (int f = fg; f < FEAT_; f += 8) {
        float x = vlad[((size_t)b * FEAT_ + f) * K_ + k];
        s += x * x;
    }
    __shared__ float red[512];
    red[t] = s;
    __syncthreads();
    if (fg == 0) {
        float tot = 0.f;
        #pragma unroll
        for (int i = 0; i < 8; i++) tot += red[i * 64 + k];
        red[k] = 1.f / fmaxf(sqrtf(tot), L2_EPS);
    }
    __syncthreads();
    float inv = red[k];
    for (int f = fg; f < FEAT_; f += 8) {
        int idx = f * K_ + k;
        float x = vlad[((size_t)b * FEAT_ + f) * K_ + k] * inv;
        vladn[(size_t)b * VLAD_ + idx] =
            (x - mm[idx]) * rsqrtf(vv[idx] + BN_EPS) * g[idx] + bb[idx];
    }
}

// ---------------- K10: broadcast bias init ----------------
__global__ void bias_init_kernel(float* __restrict__ C, const float* __restrict__ bias,
                                 int rows, int N) {
    int idx = blockIdx.x * blockDim.x + threadIdx.x;
    if (idx < rows * N) C[idx] = bias[idx % N];
}

// ---------------- K11: skinny GEMM (split-K, atomic) ----------------
__global__ void skinny32_kernel(const float* __restrict__ A, const float* __restrict__ W,
                                float* __restrict__ C, int N, int K, int KC) {
    int o0 = blockIdx.x * 128;
    int k0 = blockIdx.y * KC;
    __shared__ float As[32][36];
    __shared__ float Ws[32][132];
    int t = threadIdx.x;
    int kl = t & 31, rg = t >> 5;
    int oq = t & 31, bq = t >> 5;
    float acc[4][4];
    #pragma unroll
    for (int i = 0; i < 4; i++)
        #pragma unroll
        for (int j = 0; j < 4; j++) acc[i][j] = 0.f;

    int kend = min(k0 + KC, K);
    for (int kt = k0; kt < kend; kt += 32) {
        __syncthreads();
        #pragma unroll
        for (int i = 0; i < 4; i++) {
            int b = rg + i * 8;
            As[kl][b] = A[(size_t)b * K + kt + kl];
        }
        #pragma unroll
        for (int i = 0; i < 16; i++) {
            int o = rg + i * 8;
            int og = o0 + o;
            Ws[kl][o] = (og < N) ? W[(size_t)og * K + kt + kl] : 0.f;
        }
        __syncthreads();
        #pragma unroll
        for (int kk = 0; kk < 32; kk++) {
            float4 w4 = *(const float4*)&Ws[kk][oq * 4];
            float4 a4 = *(const float4*)&As[kk][bq * 4];
            float av[4] = {a4.x, a4.y, a4.z, a4.w};
            float wv[4] = {w4.x, w4.y, w4.z, w4.w};
            #pragma unroll
            for (int i = 0; i < 4; i++)
                #pragma unroll
                for (int j = 0; j < 4; j++) acc[i][j] += av[i] * wv[j];
        }
    }
    #pragma unroll
    for (int i = 0; i < 4; i++) {
        int b = bq * 4 + i;
        #pragma unroll
        for (int j = 0; j < 4; j++) {
            int o = o0 + oq * 4 + j;
            if (o < N) atomicAdd(&C[(size_t)b * N + o], acc[i][j]);
        }
    }
}

// ---------------- K12: BN ----------------
__global__ void bn_kernel(const float* __restrict__ in, float* __restrict__ out,
                          const float* __restrict__ g, const float* __restrict__ bb,
                          const float* __restrict__ mm, const float* __restrict__ vv,
                          int rows, int N) {
    int idx = blockIdx.x * blockDim.x + threadIdx.x;
    if (idx < rows * N) {
        int c = idx % N;
        out[idx] = (in[idx] - mm[c]) * rsqrtf(vv[c] + BN_EPS) * g[c] + bb[c];
    }
}

// ---------------- K13/K14: SE gating ----------------
__global__ void se1_kernel(const float* __restrict__ y, const float* __restrict__ w,
                           const float* __restrict__ bias,
                           const float* __restrict__ g, const float* __restrict__ bb,
                           const float* __restrict__ mm, const float* __restrict__ vv,
                           float* __restrict__ z) {
    int warp = threadIdx.x >> 5, lane = threadIdx.x & 31;
    int idx = blockIdx.x * 8 + warp;
    int b = idx / HR_, o = idx % HR_;
    const float* yr = y + (size_t)b * H_;
    const float* wr = w + (size_t)o * H_;
    float s = 0.f;
    for (int k = lane; k < H_; k += 32) s += yr[k] * wr[k];
    for (int off = 16; off; off >>= 1) s += __shfl_xor_sync(0xffffffffu, s, off);
    if (lane == 0) {
        float v = s + bias[o];
        v = (v - mm[o]) * rsqrtf(vv[o] + BN_EPS) * g[o] + bb[o];
        z[(size_t)b * HR_ + o] = fmaxf(v, 0.f);
    }
}

__global__ void se2_kernel(const float* __restrict__ z, const float* __restrict__ w,
                           const float* __restrict__ bias, const float* __restrict__ y,
                           float* __restrict__ yg) {
    int warp = threadIdx.x >> 5, lane = threadIdx.x & 31;
    int idx = blockIdx.x * 8 + warp;
    int b = idx / H_, o = idx % H_;
    const float* zr = z + (size_t)b * HR_;
    const float* wr = w + (size_t)o * HR_;
    float s = 0.f;
    for (int k = lane; k < HR_; k += 32) s += zr[k] * wr[k];
    for (int off = 16; off; off >>= 1) s += __shfl_xor_sync(0xffffffffu, s, off);
    if (lane == 0) {
        float gate = 1.f / (1.f + expf(-(s + bias[o])));
        yg[(size_t)b * H_ + o] = y[(size_t)b * H_ + o] * gate;
    }
}

// ---------------- host launcher ----------------
extern "C" void kernel_launch(void* const* d_in, const int* in_sizes, int n_in,
                              void* d_out, int out_size) {
    const float* x     = (const float*)d_in[0];
    const float* fc1_w = (const float*)d_in[1];
    const float* fc1_b = (const float*)d_in[2];
    const float* fc2_w = (const float*)d_in[3];
    const float* fc2_b = (const float*)d_in[4];
    const float* c1    = (const float*)d_in[5];
    const float* c2    = (const float*)d_in[6];
    const float* bn1_g = (const float*)d_in[7];
    const float* bn1_b = (const float*)d_in[8];
    const float* bn1_m = (const float*)d_in[9];
    const float* bn1_v = (const float*)d_in[10];
    const float* bn2_g = (const float*)d_in[11];
    const float* bn2_b = (const float*)d_in[12];
    const float* bn2_m = (const float*)d_in[13];
    const float* bn2_v = (const float*)d_in[14];
    const float* cgf_w = (const float*)d_in[15];
    const float* cgf_b = (const float*)d_in[16];
    const float* cgbn_g = (const float*)d_in[17];
    const float* cgbn_b = (const float*)d_in[18];
    const float* cgbn_m = (const float*)d_in[19];
    const float* cgbn_v = (const float*)d_in[20];
    const float* g1_w  = (const float*)d_in[21];
    const float* g1_b  = (const float*)d_in[22];
    const float* gbn_g = (const float*)d_in[23];
    const float* gbn_b = (const float*)d_in[24];
    const float* gbn_m = (const float*)d_in[25];
    const float* gbn_v = (const float*)d_in[26];
    const float* g2_w  = (const float*)d_in[27];
    const float* g2_b  = (const float*)d_in[28];
    const float* fc3_w = (const float*)d_in[29];
    const float* fc3_b = (const float*)d_in[30];
    float* out = (float*)d_out;

    float *att, *act, *asum, *vlad, *vladn, *y0, *y, *z, *yg, *w2e, *attb;
    __half *xh, *wh, *hh, *c1h, *actnh;
    cudaGetSymbolAddress((void**)&att,   g_att);
    cudaGetSymbolAddress((void**)&act,   g_act);
    cudaGetSymbolAddress((void**)&asum,  g_asum);
    cudaGetSymbolAddress((void**)&vlad,  g_vlad);
    cudaGetSymbolAddress((void**)&vladn, g_vladn);
    cudaGetSymbolAddress((void**)&y0,    g_y0);
    cudaGetSymbolAddress((void**)&y,     g_y);
    cudaGetSymbolAddress((void**)&z,     g_z);
    cudaGetSymbolAddress((void**)&yg,    g_yg);
    cudaGetSymbolAddress((void**)&w2e,   g_w2e);
    cudaGetSymbolAddress((void**)&attb,  g_attb);
    cudaGetSymbolAddress((void**)&xh,    g_xh);
    cudaGetSymbolAddress((void**)&wh,    g_wh);
    cudaGetSymbolAddress((void**)&hh,    g_hh);
    cudaGetSymbolAddress((void**)&c1h,   g_c1h);
    cudaGetSymbolAddress((void**)&actnh, g_actnh);

    cudaFuncSetAttribute((const void*)mma_gemm_kernel<0>,
                         cudaFuncAttributeMaxDynamicSharedMemorySize, GEMM_SMEM);
    cudaFuncSetAttribute((const void*)mma_gemm_kernel<1>,
                         cudaFuncAttributeMaxDynamicSharedMemorySize, GEMM_SMEM);

    // launch 1-3: fused attention weights
    zero_kernel<<<(G_ * D_ + 255) / 256, 256>>>(w2e, G_ * D_);
    fuse_attw_kernel<<<dim3(D_ / 256, ED_ / 256), 256>>>(fc1_w, fc2_w, w2e);
    fuse_attb_kernel<<<1, 256>>>(fc2_w, fc1_b, fc2_b, attb);

    // launch 4: fc1_w -> fp16
    tohalf_kernel<<<(ED_ * D_ / 4 + 255) / 256, 256>>>(fc1_w, wh, ED_ * D_);

    // launch 5: rownorm + x->fp16 + attention (fused)
    rownorm_att_kernel<<<M_, 256>>>(x, w2e, attb, xh, att);

    // launch 6 (ncu target): h = xn @ fc1_w^T + fc1_b — fp16 MMA
    mma_gemm_kernel<0><<<dim3(ED_ / BN, M_ / BM), 256, GEMM_SMEM>>>(
        xh, wh, nullptr, hh, M_, ED_, D_, fc1_b, nullptr, nullptr, nullptr);

    // launch 7: c1^T -> fp16
    transpose_half_kernel<<<dim3((G_ * K_) / 32, ED_ / 32), 256>>>(c1, c1h, ED_, G_ * K_);

    // launch 8: zero asum
    zero_kernel<<<(B_ * K_ + 255) / 256, 256>>>(asum, B_ * K_);

    // launch 9: act = BN1(h @ c1) — fp16 MMA
    mma_gemm_kernel<1><<<dim3((G_ * K_) / BN, M_ / BM), 256, GEMM_SMEM>>>(
        hh, c1h, act, nullptr, M_, G_ * K_, ED_, bn1_g, bn1_b, bn1_m, bn1_v);

    // launch 10: softmax * att -> fp16 actn + fused asum
    softmax_att_kernel<<<M_, 256>>>(act, att, actnh, asum);

    // launch 11: vlad — tensor cores
    vlad_mma_kernel<<<dim3(B_, FEAT_ / 64), 128>>>(hh, actnh, asum, c2, vlad);

    // launch 12: intra-norm + BN2
    intranorm_bn_kernel<<<B_, 512>>>(vlad, vladn, bn2_g, bn2_b, bn2_m, bn2_v);

    // launch 13-15: y = BN(vladn @ cgf_w^T + cgf_b) — 64-way split-K
    bias_init_kernel<<<(B_ * H_ + 255) / 256, 256>>>(y0, cgf_b, B_, H_);
    skinny32_kernel<<<dim3(H_ / 128, 64), 256>>>(vladn, cgf_w, y0, H_, VLAD_, VLAD_ / 64);
    bn_kernel<<<(B_ * H_ + 255) / 256, 256>>>(y0, y, cgbn_g, cgbn_b, cgbn_m, cgbn_v, B_, H_);

    // launch 16-17: SE gating
    se1_kernel<<<(B_ * HR_) / 8, 256>>>(y, g1_w, g1_b, gbn_g, gbn_b, gbn_m, gbn_v, z);
    se2_kernel<<<(B_ * H_) / 8, 256>>>(z, g2_w, g2_b, y, yg);

    // launch 18-19: out = yg @ fc3_w^T + fc3_b — 16-way split-K
    bias_init_kernel<<<(B_ * NC_ + 255) / 256, 256>>>(out, fc3_b, B_, NC_);
    skinny32_kernel<<<dim3((NC_ + 127) / 128, 16), 256>>>(yg, fc3_w, out, NC_, H_, H_ / 16);
}